// round 1
// baseline (speedup 1.0000x reference)
#include <cuda_runtime.h>

#define CC   512
#define HWW  3136
#define WW   56
#define HH   56
#define NHEADS 16
#define DH   32
#define NB   8

// Scratch (allocation-free: static __device__ globals)
__device__ float g_q[(size_t)NB * NHEADS * HWW * DH];
__device__ float g_k[(size_t)NB * NHEADS * HWW * DH];
__device__ float g_v[(size_t)NB * NHEADS * HWW * DH];
__device__ float g_ao[(size_t)NB * HWW * CC];

// ---------------------------------------------------------------------------
// Kernel 1: fused NHWC-gather + qkv GEMM.
//   qkv[m, n] = sum_k x[b, k, hw] * qkv_w[n, k],  m = b*3136 + hw, n in [0,1536)
// Output scattered into g_q (scaled by d^-0.5), g_k, g_v with layout
// [b, head, hw, d] so the attention kernel reads contiguous d-vectors.
// Tiles: BM=64, BN=64, BK=16, 256 threads, 4x4 microtile.
// ---------------------------------------------------------------------------
__global__ void qkv_gemm(const float* __restrict__ x, const float* __restrict__ w)
{
    __shared__ float As[16][64];
    __shared__ float Bs[16][65];   // +1 pad: B is loaded k-fastest (STS bank spread)

    int m0  = blockIdx.x * 64;
    int n0  = blockIdx.y * 64;
    int b   = m0 / HWW;            // 3136 % 64 == 0, so one batch per tile
    int pb0 = m0 % HWW;
    int t   = threadIdx.x;
    int tx  = t & 15, ty = t >> 4;

    float acc[4][4];
#pragma unroll
    for (int i = 0; i < 4; i++)
#pragma unroll
        for (int j = 0; j < 4; j++) acc[i][j] = 0.f;

    const float* xb = x + (size_t)b * CC * HWW + pb0;

    for (int k0 = 0; k0 < CC; k0 += 16) {
#pragma unroll
        for (int i = 0; i < 4; i++) {          // A: 64 pixels x 16 k  (coalesced over hw)
            int idx = t + 256 * i;
            int kk = idx >> 6, mm = idx & 63;
            As[kk][mm] = xb[(size_t)(k0 + kk) * HWW + mm];
        }
#pragma unroll
        for (int i = 0; i < 4; i++) {          // B: 64 n x 16 k (coalesced over k)
            int idx = t + 256 * i;
            int nn = idx >> 4, kk = idx & 15;
            Bs[kk][nn] = w[(size_t)(n0 + nn) * CC + k0 + kk];
        }
        __syncthreads();
#pragma unroll
        for (int kk = 0; kk < 16; kk++) {
            float a[4], bb[4];
            float4 a4 = *(const float4*)&As[kk][ty * 4];
            a[0] = a4.x; a[1] = a4.y; a[2] = a4.z; a[3] = a4.w;
#pragma unroll
            for (int j = 0; j < 4; j++) bb[j] = Bs[kk][tx * 4 + j];
#pragma unroll
            for (int i = 0; i < 4; i++)
#pragma unroll
                for (int j = 0; j < 4; j++)
                    acc[i][j] = fmaf(a[i], bb[j], acc[i][j]);
        }
        __syncthreads();
    }

    // Epilogue: scatter to q/k/v planes. n-tile (64) never crosses the q/k/v
    // boundary (512 | 64) nor a head boundary within a float4 (dd % 4 == 0).
    int nb   = n0 + tx * 4;
    int sel  = nb >> 9;
    int c512 = nb & 511;
    int head = c512 >> 5;
    int dd   = c512 & 31;
    float scl = 1.0f;
    float* dst;
    if (sel == 0)      { dst = g_q; scl = 0.17677669529663687f; }  // 32^-0.5
    else if (sel == 1) { dst = g_k; }
    else               { dst = g_v; }
    size_t plane = ((size_t)b * NHEADS + head) * HWW;
#pragma unroll
    for (int i = 0; i < 4; i++) {
        int hw = pb0 + ty * 4 + i;
        float4 v4 = make_float4(acc[i][0] * scl, acc[i][1] * scl,
                                acc[i][2] * scl, acc[i][3] * scl);
        *(float4*)(dst + (plane + hw) * DH + dd) = v4;
    }
}

// ---------------------------------------------------------------------------
// Kernel 2: neighborhood attention.
// Block = one (b,head) and a 4x8 pixel tile. k/v halo region (10 rows x 14
// cols x 32 dims) staged in smem (2 x 17.5 KB). One warp per (row-half):
// warps 0..7 -> (row = w>>1, 4 columns = (w&1)*4..+3). Lane = head-dim.
// 49 logits per pixel via shfl-xor dot reductions; softmax in registers;
// AV accumulation from smem v tile. Output written pixel-major [p, C] for
// the proj GEMM.
// ---------------------------------------------------------------------------
__global__ void attn_kernel(const float* __restrict__ rpb)
{
    __shared__ float ks[10 * 14 * 32];
    __shared__ float vs[10 * 14 * 32];
    __shared__ float rs[169];

    int bh   = blockIdx.z;                 // b*16 + head
    int head = bh & (NHEADS - 1);
    int bb   = bh >> 4;
    int i0   = blockIdx.y * 4;
    int j0   = blockIdx.x * 8;
    int rstart = max(0, min(i0 - 3, HH - 10));
    int cstart = max(0, min(j0 - 3, WW - 14));

    const float* kp = g_k + (size_t)bh * HWW * DH;
    const float* vp = g_v + (size_t)bh * HWW * DH;

    for (int idx = threadIdx.x; idx < 10 * 14 * 32; idx += 256) {
        int r   = idx / 448;               // 448 = 14*32 floats per halo row
        int rem = idx - r * 448;
        size_t g = ((size_t)(rstart + r) * WW + cstart) * DH + rem;
        ks[idx] = kp[g];
        vs[idx] = vp[g];
    }
    for (int idx = threadIdx.x; idx < 169; idx += 256)
        rs[idx] = rpb[head * 169 + idx];
    __syncthreads();

    int warp = threadIdx.x >> 5, lane = threadIdx.x & 31;
    int i  = i0 + (warp >> 1);
    int si = min(max(i - 3, 0), HH - 7);
    const float* qrow = g_q + ((size_t)bh * HWW + (size_t)i * WW) * DH;

    for (int cc = 0; cc < 4; cc++) {
        int j  = j0 + (warp & 1) * 4 + cc;
        int sj = min(max(j - 3, 0), WW - 7);
        float qv = qrow[j * DH + lane];

        float lg[49];
        int bi = (si - i + 6) * 13 + (sj - j + 6);
#pragma unroll
        for (int a = 0; a < 7; a++) {
            int rb = ((si + a - rstart) * 14 + (sj - cstart)) * DH;
#pragma unroll
            for (int c = 0; c < 7; c++) {
                float p = qv * ks[rb + c * DH + lane];
                p += __shfl_xor_sync(0xffffffffu, p, 16);
                p += __shfl_xor_sync(0xffffffffu, p, 8);
                p += __shfl_xor_sync(0xffffffffu, p, 4);
                p += __shfl_xor_sync(0xffffffffu, p, 2);
                p += __shfl_xor_sync(0xffffffffu, p, 1);
                lg[a * 7 + c] = p + rs[bi + a * 13 + c];
            }
        }

        float mx = lg[0];
#pragma unroll
        for (int tt = 1; tt < 49; tt++) mx = fmaxf(mx, lg[tt]);
        float s = 0.f;
#pragma unroll
        for (int tt = 0; tt < 49; tt++) { lg[tt] = __expf(lg[tt] - mx); s += lg[tt]; }
        float inv = 1.0f / s;

        float acc = 0.f;
#pragma unroll
        for (int a = 0; a < 7; a++) {
            int rb = ((si + a - rstart) * 14 + (sj - cstart)) * DH;
#pragma unroll
            for (int c = 0; c < 7; c++)
                acc = fmaf(lg[a * 7 + c], vs[rb + c * DH + lane], acc);
        }
        acc *= inv;

        size_t pg = (size_t)bb * HWW + (size_t)i * WW + j;
        g_ao[pg * CC + head * DH + lane] = acc;
    }
}

// ---------------------------------------------------------------------------
// Kernel 3: proj GEMM + bias + transpose-store to NCHW output.
//   y[b, n, hw] = sum_k ao[m, k] * proj_w[n, k] + bias[n]
// A is row-major [P, 512] -> loaded k-fastest into padded smem.
// ---------------------------------------------------------------------------
__global__ void proj_gemm(const float* __restrict__ w, const float* __restrict__ bias,
                          float* __restrict__ y)
{
    __shared__ float As[16][65];
    __shared__ float Bs[16][65];

    int m0  = blockIdx.x * 64;
    int n0  = blockIdx.y * 64;
    int b   = m0 / HWW;
    int pb0 = m0 % HWW;
    int t   = threadIdx.x;
    int tx  = t & 15, ty = t >> 4;

    float acc[4][4];
#pragma unroll
    for (int i = 0; i < 4; i++)
#pragma unroll
        for (int j = 0; j < 4; j++) acc[i][j] = 0.f;

    const float* A = g_ao + (size_t)m0 * CC;

    for (int k0 = 0; k0 < CC; k0 += 16) {
#pragma unroll
        for (int i = 0; i < 4; i++) {          // A: k-fastest (coalesced), padded STS
            int idx = t + 256 * i;
            int mm = idx >> 4, kk = idx & 15;
            As[kk][mm] = A[(size_t)mm * CC + k0 + kk];
        }
#pragma unroll
        for (int i = 0; i < 4; i++) {
            int idx = t + 256 * i;
            int nn = idx >> 4, kk = idx & 15;
            Bs[kk][nn] = w[(size_t)(n0 + nn) * CC + k0 + kk];
        }
        __syncthreads();
#pragma unroll
        for (int kk = 0; kk < 16; kk++) {
            float a[4], bb[4];
#pragma unroll
            for (int i = 0; i < 4; i++) a[i] = As[kk][ty * 4 + i];
#pragma unroll
            for (int j = 0; j < 4; j++) bb[j] = Bs[kk][tx * 4 + j];
#pragma unroll
            for (int i = 0; i < 4; i++)
#pragma unroll
                for (int j = 0; j < 4; j++)
                    acc[i][j] = fmaf(a[i], bb[j], acc[i][j]);
        }
        __syncthreads();
    }

    // Transposed store: for each output channel n, the 4 m-consecutive values
    // form a contiguous float4 along hw.
#pragma unroll
    for (int jj = 0; jj < 4; jj++) {
        int n = n0 + tx * 4 + jj;
        float bv = bias[n];
        float4 v4 = make_float4(acc[0][jj] + bv, acc[1][jj] + bv,
                                acc[2][jj] + bv, acc[3][jj] + bv);
        *(float4*)(y + ((size_t)b * CC + n) * HWW + pb0 + ty * 4) = v4;
    }
}

// ---------------------------------------------------------------------------
extern "C" void kernel_launch(void* const* d_in, const int* in_sizes, int n_in,
                              void* d_out, int out_size)
{
    const float* x      = (const float*)d_in[0];
    const float* qkv_w  = (const float*)d_in[1];
    const float* rpb    = (const float*)d_in[2];
    const float* proj_w = (const float*)d_in[3];
    const float* proj_b = (const float*)d_in[4];
    float* y = (float*)d_out;

    qkv_gemm <<<dim3(392, 24), 256>>>(x, qkv_w);
    attn_kernel<<<dim3(7, 14, NB * NHEADS), 256>>>(rpb);
    proj_gemm <<<dim3(392, 8), 256>>>(proj_w, proj_b, y);
}

// round 2
// speedup vs baseline: 2.5188x; 2.5188x over previous
#include <cuda_runtime.h>
#include <stdint.h>

#define CC   512
#define HWW  3136
#define WW   56
#define HH   56
#define NHEADS 16
#define DH   32
#define NB   8

// Scratch (allocation-free: static __device__ globals)
__device__ float g_q[(size_t)NB * NHEADS * HWW * DH];
__device__ float g_k[(size_t)NB * NHEADS * HWW * DH];
__device__ float g_v[(size_t)NB * NHEADS * HWW * DH];
__device__ float g_ao[(size_t)NB * HWW * CC];

// ---------------------------------------------------------------------------
// tf32 helpers
// ---------------------------------------------------------------------------
__device__ __forceinline__ float to_tf32(float x) {
    float y;
    asm("cvt.rna.tf32.f32 %0, %1;" : "=f"(y) : "f"(x));
    return y;
}
__device__ __forceinline__ float4 to_tf32_4(float4 v) {
    return make_float4(to_tf32(v.x), to_tf32(v.y), to_tf32(v.z), to_tf32(v.w));
}
__device__ __forceinline__ void mma_tf32(float c[4], uint32_t a0, uint32_t a1,
                                         uint32_t a2, uint32_t a3,
                                         uint32_t b0, uint32_t b1) {
    asm volatile(
        "mma.sync.aligned.m16n8k8.row.col.f32.tf32.tf32.f32 "
        "{%0,%1,%2,%3}, {%4,%5,%6,%7}, {%8,%9}, {%0,%1,%2,%3};\n"
        : "+f"(c[0]), "+f"(c[1]), "+f"(c[2]), "+f"(c[3])
        : "r"(a0), "r"(a1), "r"(a2), "r"(a3), "r"(b0), "r"(b1));
}

// ---------------------------------------------------------------------------
// Kernel 1: fused NHWC-gather + qkv GEMM (tf32 tensor cores).
//   qkv[m, n] = sum_k x[b, k, hw] * qkv_w[n, k]
// BM=64 (divides 3136), BN=256, BK=32. 8 warps, each computing a 64x32 warp
// tile as 4(m) x 4(n) m16n8k8 MMAs per k-step (4 k-steps per BK).
// As: [k][m], row stride 72 floats (conflict-free frag reads: bank=8k+m).
// Bs: [n][k], row stride 36 floats (bank = 4n+k, conflict-free).
// Epilogue scatters to g_q (scaled), g_k, g_v in [b, head, hw, d] layout.
// ---------------------------------------------------------------------------
__global__ __launch_bounds__(256, 2)
void qkv_gemm_tc(const float* __restrict__ x, const float* __restrict__ w)
{
    __shared__ float As[32 * 72];
    __shared__ float Bs[256 * 36];

    int m0 = blockIdx.x * 64;
    int n0 = blockIdx.y * 256;
    int b  = m0 / HWW;
    int pb0 = m0 % HWW;
    int t = threadIdx.x;
    int warp = t >> 5, lane = t & 31;
    int tg = lane & 3, g = lane >> 2;

    float c[4][4][4];
#pragma unroll
    for (int mt = 0; mt < 4; mt++)
#pragma unroll
        for (int nt = 0; nt < 4; nt++)
#pragma unroll
            for (int r = 0; r < 4; r++) c[mt][nt][r] = 0.f;

    const float* xb = x + (size_t)b * CC * HWW + pb0;

    for (int k0 = 0; k0 < CC; k0 += 32) {
        // ---- global loads to regs ----
        float4 av[2];
#pragma unroll
        for (int p = 0; p < 2; p++) {
            int kk = (t >> 4) + p * 16;
            int m4 = (t & 15) * 4;
            av[p] = *(const float4*)(xb + (size_t)(k0 + kk) * HWW + m4);
        }
        float4 bv[8];
#pragma unroll
        for (int i = 0; i < 8; i++) {
            int idx = t + 256 * i;
            int nn = idx >> 3;
            int k4 = (idx & 7) * 4;
            bv[i] = *(const float4*)(w + (size_t)(n0 + nn) * CC + k0 + k4);
        }
        __syncthreads();   // previous iteration's MMA reads done
        // ---- stage (with tf32 rounding) ----
#pragma unroll
        for (int p = 0; p < 2; p++) {
            int kk = (t >> 4) + p * 16;
            int m4 = (t & 15) * 4;
            *(float4*)&As[kk * 72 + m4] = to_tf32_4(av[p]);
        }
#pragma unroll
        for (int i = 0; i < 8; i++) {
            int idx = t + 256 * i;
            int nn = idx >> 3;
            int k4 = (idx & 7) * 4;
            *(float4*)&Bs[nn * 36 + k4] = to_tf32_4(bv[i]);
        }
        __syncthreads();
        // ---- MMA ----
#pragma unroll
        for (int ks = 0; ks < 4; ks++) {
            int kb = ks * 8;
            uint32_t a[4][4];
#pragma unroll
            for (int mt = 0; mt < 4; mt++) {
                int mb = mt * 16 + g;
                a[mt][0] = __float_as_uint(As[(kb + tg) * 72 + mb]);
                a[mt][1] = __float_as_uint(As[(kb + tg) * 72 + mb + 8]);
                a[mt][2] = __float_as_uint(As[(kb + tg + 4) * 72 + mb]);
                a[mt][3] = __float_as_uint(As[(kb + tg + 4) * 72 + mb + 8]);
            }
            uint32_t bq[4][2];
#pragma unroll
            for (int nt = 0; nt < 4; nt++) {
                int nn = warp * 32 + nt * 8 + g;
                bq[nt][0] = __float_as_uint(Bs[nn * 36 + kb + tg]);
                bq[nt][1] = __float_as_uint(Bs[nn * 36 + kb + tg + 4]);
            }
#pragma unroll
            for (int mt = 0; mt < 4; mt++)
#pragma unroll
                for (int nt = 0; nt < 4; nt++)
                    mma_tf32(c[mt][nt], a[mt][0], a[mt][1], a[mt][2], a[mt][3],
                             bq[nt][0], bq[nt][1]);
        }
    }

    // ---- epilogue: warp covers exactly 32 n = one (sel, head) ----
    int nwb  = n0 + warp * 32;
    int sel  = nwb >> 9;
    int head = (nwb & 511) >> 5;
    float scl = (sel == 0) ? 0.17677669529663687f : 1.0f;
    float* dst = (sel == 0) ? g_q : (sel == 1) ? g_k : g_v;
    size_t plane = ((size_t)b * NHEADS + head) * HWW;
#pragma unroll
    for (int mt = 0; mt < 4; mt++) {
#pragma unroll
        for (int h = 0; h < 2; h++) {
            int hw = pb0 + mt * 16 + g + h * 8;
            float* row = dst + (plane + hw) * DH;
#pragma unroll
            for (int nt = 0; nt < 4; nt++) {
                int dd = nt * 8 + 2 * tg;
                float2 v2 = make_float2(c[mt][nt][h * 2] * scl,
                                        c[mt][nt][h * 2 + 1] * scl);
                *(float2*)(row + dd) = v2;
            }
        }
    }
}

// ---------------------------------------------------------------------------
// Kernel 2: neighborhood attention (unchanged fp32 design).
// ---------------------------------------------------------------------------
__global__ void attn_kernel(const float* __restrict__ rpb)
{
    __shared__ float ks[10 * 14 * 32];
    __shared__ float vs[10 * 14 * 32];
    __shared__ float rs[169];

    int bh   = blockIdx.z;
    int head = bh & (NHEADS - 1);
    int bb   = bh >> 4;
    int i0   = blockIdx.y * 4;
    int j0   = blockIdx.x * 8;
    int rstart = max(0, min(i0 - 3, HH - 10));
    int cstart = max(0, min(j0 - 3, WW - 14));

    const float* kp = g_k + (size_t)bh * HWW * DH;
    const float* vp = g_v + (size_t)bh * HWW * DH;

    for (int idx = threadIdx.x; idx < 10 * 14 * 32; idx += 256) {
        int r   = idx / 448;
        int rem = idx - r * 448;
        size_t gofs = ((size_t)(rstart + r) * WW + cstart) * DH + rem;
        ks[idx] = kp[gofs];
        vs[idx] = vp[gofs];
    }
    for (int idx = threadIdx.x; idx < 169; idx += 256)
        rs[idx] = rpb[head * 169 + idx];
    __syncthreads();

    int warp = threadIdx.x >> 5, lane = threadIdx.x & 31;
    int i  = i0 + (warp >> 1);
    int si = min(max(i - 3, 0), HH - 7);
    const float* qrow = g_q + ((size_t)bh * HWW + (size_t)i * WW) * DH;

    for (int cc = 0; cc < 4; cc++) {
        int j  = j0 + (warp & 1) * 4 + cc;
        int sj = min(max(j - 3, 0), WW - 7);
        float qv = qrow[j * DH + lane];

        float lg[49];
        int bi = (si - i + 6) * 13 + (sj - j + 6);
#pragma unroll
        for (int a = 0; a < 7; a++) {
            int rb = ((si + a - rstart) * 14 + (sj - cstart)) * DH;
#pragma unroll
            for (int cq = 0; cq < 7; cq++) {
                float p = qv * ks[rb + cq * DH + lane];
                p += __shfl_xor_sync(0xffffffffu, p, 16);
                p += __shfl_xor_sync(0xffffffffu, p, 8);
                p += __shfl_xor_sync(0xffffffffu, p, 4);
                p += __shfl_xor_sync(0xffffffffu, p, 2);
                p += __shfl_xor_sync(0xffffffffu, p, 1);
                lg[a * 7 + cq] = p + rs[bi + a * 13 + cq];
            }
        }

        float mx = lg[0];
#pragma unroll
        for (int tt = 1; tt < 49; tt++) mx = fmaxf(mx, lg[tt]);
        float s = 0.f;
#pragma unroll
        for (int tt = 0; tt < 49; tt++) { lg[tt] = __expf(lg[tt] - mx); s += lg[tt]; }
        float inv = 1.0f / s;

        float acc = 0.f;
#pragma unroll
        for (int a = 0; a < 7; a++) {
            int rb = ((si + a - rstart) * 14 + (sj - cstart)) * DH;
#pragma unroll
            for (int cq = 0; cq < 7; cq++)
                acc = fmaf(lg[a * 7 + cq], vs[rb + cq * DH + lane], acc);
        }
        acc *= inv;

        size_t pg = (size_t)bb * HWW + (size_t)i * WW + j;
        g_ao[pg * CC + head * DH + lane] = acc;
    }
}

// ---------------------------------------------------------------------------
// Kernel 3: proj GEMM (tf32 tensor cores) + bias + NCHW transpose-store.
//   y[b, n, hw] = sum_k ao[m, k] * proj_w[n, k] + bias[n]
// As: [m][k] stride 36 (A global is k-contiguous, same layout as B).
// ---------------------------------------------------------------------------
__global__ __launch_bounds__(256, 2)
void proj_gemm_tc(const float* __restrict__ w, const float* __restrict__ bias,
                  float* __restrict__ y)
{
    __shared__ float As[64 * 36];
    __shared__ float Bs[256 * 36];

    int m0 = blockIdx.x * 64;
    int n0 = blockIdx.y * 256;
    int b  = m0 / HWW;
    int pb0 = m0 % HWW;
    int t = threadIdx.x;
    int warp = t >> 5, lane = t & 31;
    int tg = lane & 3, g = lane >> 2;

    float c[4][4][4];
#pragma unroll
    for (int mt = 0; mt < 4; mt++)
#pragma unroll
        for (int nt = 0; nt < 4; nt++)
#pragma unroll
            for (int r = 0; r < 4; r++) c[mt][nt][r] = 0.f;

    const float* A = g_ao + (size_t)m0 * CC;

    for (int k0 = 0; k0 < CC; k0 += 32) {
        float4 av[2];
#pragma unroll
        for (int p = 0; p < 2; p++) {
            int idx = t + 256 * p;
            int mm = idx >> 3;
            int k4 = (idx & 7) * 4;
            av[p] = *(const float4*)(A + (size_t)mm * CC + k0 + k4);
        }
        float4 bv[8];
#pragma unroll
        for (int i = 0; i < 8; i++) {
            int idx = t + 256 * i;
            int nn = idx >> 3;
            int k4 = (idx & 7) * 4;
            bv[i] = *(const float4*)(w + (size_t)(n0 + nn) * CC + k0 + k4);
        }
        __syncthreads();
#pragma unroll
        for (int p = 0; p < 2; p++) {
            int idx = t + 256 * p;
            int mm = idx >> 3;
            int k4 = (idx & 7) * 4;
            *(float4*)&As[mm * 36 + k4] = to_tf32_4(av[p]);
        }
#pragma unroll
        for (int i = 0; i < 8; i++) {
            int idx = t + 256 * i;
            int nn = idx >> 3;
            int k4 = (idx & 7) * 4;
            *(float4*)&Bs[nn * 36 + k4] = to_tf32_4(bv[i]);
        }
        __syncthreads();
#pragma unroll
        for (int ks = 0; ks < 4; ks++) {
            int kb = ks * 8;
            uint32_t a[4][4];
#pragma unroll
            for (int mt = 0; mt < 4; mt++) {
                int mb = mt * 16 + g;
                a[mt][0] = __float_as_uint(As[mb * 36 + kb + tg]);
                a[mt][1] = __float_as_uint(As[(mb + 8) * 36 + kb + tg]);
                a[mt][2] = __float_as_uint(As[mb * 36 + kb + tg + 4]);
                a[mt][3] = __float_as_uint(As[(mb + 8) * 36 + kb + tg + 4]);
            }
            uint32_t bq[4][2];
#pragma unroll
            for (int nt = 0; nt < 4; nt++) {
                int nn = warp * 32 + nt * 8 + g;
                bq[nt][0] = __float_as_uint(Bs[nn * 36 + kb + tg]);
                bq[nt][1] = __float_as_uint(Bs[nn * 36 + kb + tg + 4]);
            }
#pragma unroll
            for (int mt = 0; mt < 4; mt++)
#pragma unroll
                for (int nt = 0; nt < 4; nt++)
                    mma_tf32(c[mt][nt], a[mt][0], a[mt][1], a[mt][2], a[mt][3],
                             bq[nt][0], bq[nt][1]);
        }
    }

    // ---- epilogue: NCHW store with bias ----
#pragma unroll
    for (int nt = 0; nt < 4; nt++) {
        int n = n0 + warp * 32 + nt * 8 + 2 * tg;
        float bv0 = bias[n];
        float bv1 = bias[n + 1];
        float* y0 = y + ((size_t)b * CC + n) * HWW;
        float* y1 = y0 + HWW;
#pragma unroll
        for (int mt = 0; mt < 4; mt++) {
#pragma unroll
            for (int h = 0; h < 2; h++) {
                int hw = pb0 + mt * 16 + g + h * 8;
                y0[hw] = c[mt][nt][h * 2]     + bv0;
                y1[hw] = c[mt][nt][h * 2 + 1] + bv1;
            }
        }
    }
}

// ---------------------------------------------------------------------------
extern "C" void kernel_launch(void* const* d_in, const int* in_sizes, int n_in,
                              void* d_out, int out_size)
{
    const float* x      = (const float*)d_in[0];
    const float* qkv_w  = (const float*)d_in[1];
    const float* rpb    = (const float*)d_in[2];
    const float* proj_w = (const float*)d_in[3];
    const float* proj_b = (const float*)d_in[4];
    float* y = (float*)d_out;

    qkv_gemm_tc<<<dim3(392, 6), 256>>>(x, qkv_w);
    attn_kernel<<<dim3(7, 14, NB * NHEADS), 256>>>(rpb);
    proj_gemm_tc<<<dim3(392, 2), 256>>>(proj_w, proj_b, y);
}